// round 3
// baseline (speedup 1.0000x reference)
#include <cuda_runtime.h>
#include <cuda_bf16.h>
#include <math.h>
#include <cstdint>

// Problem constants
#define BB 128
#define NN 64
#define DD 768
#define HH 32
#define DK 24
#define LL 4
#define TE 32
#define TD 40
#define VP 512

// ---------------- scratch (device globals; no allocations allowed) -------------
__device__ float g_q[BB*HH*NN*DK];   // [b,h,n,d]
__device__ float g_k[BB*HH*NN*DK];
__device__ float g_v[BB*HH*NN*DK];
__device__ float g_pb[BB*HH*NN*NN];  // path bias [b,h,i,j]
__device__ uint32_t g_a32[8192*768];    // node_reps as tf32
__device__ uint32_t g_wq32[2304*768];   // W_qkv transposed [n][k], tf32
__device__ uint32_t g_wo32[768*768];    // W_out transposed [n][k], tf32
__device__ uint32_t g_z32[8192*768];    // z as tf32, [b*n][h*dk]

// ---------------- tf32 helpers ---------------------------------------------------
__device__ __forceinline__ uint32_t f2tf32(float f) {
    uint32_t r;
    asm("cvt.rna.tf32.f32 %0, %1;" : "=r"(r) : "f"(f));
    return r;
}

__device__ __forceinline__ void mma_tf32(float* d, const uint32_t* a, const uint32_t* b) {
    asm volatile("mma.sync.aligned.m16n8k8.row.col.f32.tf32.tf32.f32 "
        "{%0,%1,%2,%3}, {%4,%5,%6,%7}, {%8,%9}, {%0,%1,%2,%3};"
        : "+f"(d[0]), "+f"(d[1]), "+f"(d[2]), "+f"(d[3])
        : "r"(a[0]), "r"(a[1]), "r"(a[2]), "r"(a[3]), "r"(b[0]), "r"(b[1]));
}

__device__ __forceinline__ void cp16(uint32_t saddr, const void* g) {
    asm volatile("cp.async.ca.shared.global [%0], [%1], 16;" :: "r"(saddr), "l"(g));
}

// ---------------- conversion pre-passes -----------------------------------------
__global__ void __launch_bounds__(256) conv_a_kernel(const float* __restrict__ X) {
    int idx = (blockIdx.x * 256 + threadIdx.x) * 4;
    float4 v = *(const float4*)(X + idx);
    uint4 o = { f2tf32(v.x), f2tf32(v.y), f2tf32(v.z), f2tf32(v.w) };
    *(uint4*)(g_a32 + idx) = o;
}

template<int NLD>
__global__ void convT_kernel(const float* __restrict__ W, uint32_t* __restrict__ Wt) {
    __shared__ float t[32][33];
    int k0 = blockIdx.y * 32, n0 = blockIdx.x * 32;
    int x = threadIdx.x, y = threadIdx.y;  // 32x8
    for (int yy = y; yy < 32; yy += 8)
        t[yy][x] = W[(k0 + yy) * NLD + n0 + x];
    __syncthreads();
    for (int yy = y; yy < 32; yy += 8)
        Wt[(n0 + yy) * 768 + k0 + x] = f2tf32(t[x][yy]);
}

// ---------------- pipelined tensor-core GEMM ------------------------------------
// C[8192, NOUT] = A[8192,768] @ Wt^T, A and Wt pre-converted tf32, both K-major.
// CTA 128x128, 8 warps (2x4), warp tile 64x32, 2-stage cp.async pipeline.
template<bool QKV>
__global__ void __launch_bounds__(256, 2) mma_gemm_kernel(const uint32_t* __restrict__ A,
                                                          const uint32_t* __restrict__ Bt,
                                                          const float* __restrict__ bias,
                                                          float* __restrict__ Cout) {
    extern __shared__ uint32_t sm[];
    uint32_t* Abuf = sm;                 // [2][128*36]
    uint32_t* Bbuf = sm + 2 * 128 * 36;  // [2][128*36]
    int tid = threadIdx.x;
    int wid = tid >> 5, lane = tid & 31;
    int group = lane >> 2, four = lane & 3;
    int wm = (wid >> 2) * 64, wn = (wid & 3) * 32;
    int m0 = blockIdx.y * 128, c0 = blockIdx.x * 128;

    uint32_t sbase;
    { uint64_t a = __cvta_generic_to_shared(sm); sbase = (uint32_t)a; }

    int ldrow = tid >> 1;                 // 0..127 (2 threads per row)
    int ldch4 = (tid & 1) * 16;           // u32 offset of first chunk (0 or 16)
    const uint32_t* Arow = A + (m0 + ldrow) * 768 + ldch4;
    const uint32_t* Brow = Bt + (c0 + ldrow) * 768 + ldch4;
    uint32_t sArow = sbase + (ldrow * 36 + ldch4) * 4;
    uint32_t sBrow = sbase + (2 * 128 * 36 + ldrow * 36 + ldch4) * 4;

    // prologue: stage 0
    #pragma unroll
    for (int c = 0; c < 4; c++) {
        cp16(sArow + c * 16, Arow + c * 4);
        cp16(sBrow + c * 16, Brow + c * 4);
    }
    asm volatile("cp.async.commit_group;");

    float acc[4][4][4] = {};
    #pragma unroll 1
    for (int s = 0; s < 24; s++) {
        int buf = s & 1;
        if (s + 1 < 24) {
            int nb = (s + 1) & 1;
            uint32_t soA = sArow + nb * (128 * 36 * 4);
            uint32_t soB = sBrow + nb * (128 * 36 * 4);
            const uint32_t* gA = Arow + (s + 1) * 32;
            const uint32_t* gB = Brow + (s + 1) * 32;
            #pragma unroll
            for (int c = 0; c < 4; c++) {
                cp16(soA + c * 16, gA + c * 4);
                cp16(soB + c * 16, gB + c * 4);
            }
            asm volatile("cp.async.commit_group;");
            asm volatile("cp.async.wait_group 1;");
        } else {
            asm volatile("cp.async.wait_group 0;");
        }
        __syncthreads();
        const uint32_t* As = Abuf + buf * (128 * 36);
        const uint32_t* Bs = Bbuf + buf * (128 * 36);
        #pragma unroll
        for (int ks = 0; ks < 4; ks++) {
            int kk = ks * 8;
            uint32_t af[4][4], bf[4][2];
            #pragma unroll
            for (int fm = 0; fm < 4; fm++) {
                int r = wm + fm * 16 + group;
                af[fm][0] = As[r * 36 + kk + four];
                af[fm][1] = As[(r + 8) * 36 + kk + four];
                af[fm][2] = As[r * 36 + kk + four + 4];
                af[fm][3] = As[(r + 8) * 36 + kk + four + 4];
            }
            #pragma unroll
            for (int fn = 0; fn < 4; fn++) {
                int n = wn + fn * 8 + group;
                bf[fn][0] = Bs[n * 36 + kk + four];
                bf[fn][1] = Bs[n * 36 + kk + four + 4];
            }
            #pragma unroll
            for (int fm = 0; fm < 4; fm++)
                #pragma unroll
                for (int fn = 0; fn < 4; fn++)
                    mma_tf32(acc[fm][fn], af[fm], bf[fn]);
        }
        __syncthreads();
    }
    // epilogue
    #pragma unroll
    for (int fm = 0; fm < 4; fm++) {
        #pragma unroll
        for (int fn = 0; fn < 4; fn++) {
            #pragma unroll
            for (int r = 0; r < 4; r++) {
                int m = m0 + wm + fm * 16 + group + ((r >> 1) ? 8 : 0);
                int c = c0 + wn + fn * 8 + four * 2 + (r & 1);
                float val = acc[fm][fn][r] + bias[c];
                if (QKV) {
                    int b = m >> 6, n = m & 63;
                    int sx = c / 768, rem = c - sx * 768;
                    int h = rem / 24, d = rem % 24;
                    float* dst = (sx == 0) ? g_q : (sx == 1) ? g_k : g_v;
                    dst[((b * HH + h) * NN + n) * DK + d] = val;
                } else {
                    Cout[m * 768 + c] = val;
                }
            }
        }
    }
}

// ---------------- Kernel B: path bias -------------------------------------------
__global__ void __launch_bounds__(256) path_kernel(const int* __restrict__ traj,
                                                   const int* __restrict__ distv,
                                                   const float* __restrict__ pemb,
                                                   const float* __restrict__ ppw) {
    extern __shared__ float ps[];
    float* pe = ps;                  // 512*32
    float* stage = ps + VP * HH;     // 64*33
    int b = blockIdx.x >> 1;
    int i0 = (blockIdx.x & 1) * 32;
    int tid = threadIdx.x;
    for (int e = tid; e < VP * HH; e += 256) pe[e] = pemb[e];
    int w = tid >> 5, lane = tid & 31;
    float w0 = ppw[lane], w1 = ppw[32 + lane], w2 = ppw[64 + lane], w3 = ppw[96 + lane];
    __syncthreads();
    for (int ii = 0; ii < 32; ii++) {
        int i = i0 + ii;
        #pragma unroll
        for (int jj = 0; jj < 8; jj++) {
            int j = w * 8 + jj;
            int base = (((b * NN + i) * NN) + j) * 12;
            int myidx = (lane < 12) ? traj[base + lane] : 0;
            float acc = 0.f;
            #pragma unroll
            for (int t = 0; t < 12; t++) {
                int id = __shfl_sync(0xffffffffu, myidx, t);
                float wl = (t < 3) ? w0 : (t < 6) ? w1 : (t < 9) ? w2 : w3;
                acc += pe[id * 32 + lane] * wl;
            }
            float dn = fmaxf((float)distv[(b * NN + i) * NN + j], 1.f);
            stage[j * 33 + lane] = acc / dn;
        }
        __syncthreads();
        for (int e = tid; e < HH * NN; e += 256) {
            int hh = e >> 6, j = e & 63;
            g_pb[(((b * HH + hh) * NN + i) << 6) + j] = stage[j * 33 + hh];
        }
        __syncthreads();
    }
}

// ---------------- Kernel C: attention per (b,h) ---------------------------------
#define TS 25   // padded table / k stride (conflict-free lane-strided access)
struct AttnSmem {
    float q[NN*DK], k25[NN*TS], v[NN*DK];
    float ektab[TE*TS], eqtab[TE*TS];
    float dktab[TD*TS], dqtab[TD*TS];
    float evtab[TE*TS], dvtab[TD*TS];
    float eqb[NN*TE];                   // q_i . ektab[t]   [i][t]
    float dqb[NN*TD];                   // q_i . dktab[t]   [i][t]
    float ekb_se[NN*TE];                // phase1-2: k_j . eqtab[t] [j][t]; later s_e [i][t]
    float dkb_sd[NN*TD];                // phase1-2: k_j . dqtab[t] [j][t]; later s_d [i][t]
    float amat[NN*NN];
    float trow[NN], tcol[NN];
    unsigned char ct[NN*NN], dt[NN*NN], maskv[NN];
};

__global__ void __launch_bounds__(256) attn_kernel(const int* __restrict__ conn,
                                                   const int* __restrict__ distv,
                                                   const unsigned char* __restrict__ mask,
                                                   const float* __restrict__ Eq, const float* __restrict__ Ek,
                                                   const float* __restrict__ Dq, const float* __restrict__ Dk,
                                                   const float* __restrict__ Ev, const float* __restrict__ Dv,
                                                   const float* __restrict__ Tr, const float* __restrict__ Tc) {
    extern __shared__ char sraw[];
    AttnSmem& S = *reinterpret_cast<AttnSmem*>(sraw);
    int h = blockIdx.x, b = blockIdx.y;
    int tid = threadIdx.x;
    int w = tid >> 5, lane = tid & 31;
    int qoff = (b * HH + h) * NN * DK;
    for (int e = tid; e < NN * DK; e += 256) {
        int n = e / 24, d = e - n * 24;
        S.q[e] = g_q[qoff + e];
        S.k25[n * TS + d] = g_k[qoff + e];
        S.v[e] = g_v[qoff + e];
    }
    for (int e = tid; e < TE * DK; e += 256) {
        int t = e / 24, d = e - t * 24;
        S.ektab[t*TS+d] = Ek[(t * HH + h) * DK + d];
        S.eqtab[t*TS+d] = Eq[(t * HH + h) * DK + d];
        S.evtab[t*TS+d] = Ev[(t * HH + h) * DK + d];
    }
    for (int e = tid; e < TD * DK; e += 256) {
        int t = e / 24, d = e - t * 24;
        S.dktab[t*TS+d] = Dk[(t * HH + h) * DK + d];
        S.dqtab[t*TS+d] = Dq[(t * HH + h) * DK + d];
        S.dvtab[t*TS+d] = Dv[(t * HH + h) * DK + d];
    }
    if (tid < NN) {
        S.trow[tid] = Tr[h * NN + tid];
        S.tcol[tid] = Tc[h * NN + tid];
        S.maskv[tid] = mask[b * NN + tid];
    }
    int cdoff = b * NN * NN;
    int pboff = (b * HH + h) * NN * NN;
    for (int e = tid; e < NN * NN; e += 256) {
        S.ct[e] = (unsigned char)conn[cdoff + e];
        S.dt[e] = (unsigned char)distv[cdoff + e];
        S.amat[e] = g_pb[pboff + e];
    }
    __syncthreads();
    // phase 1: per-type bias tables, warp-row register blocking
    {
        #pragma unroll 1
        for (int r = 0; r < 8; r++) {
            int i = w * 8 + r;
            float qr[24], kr[24];
            #pragma unroll
            for (int d = 0; d < 24; d++) { qr[d] = S.q[i*24+d]; kr[d] = S.k25[i*TS+d]; }
            float s0 = 0.f, s1 = 0.f;
            #pragma unroll
            for (int d = 0; d < 24; d++) {
                s0 += qr[d] * S.ektab[lane*TS+d];
                s1 += kr[d] * S.eqtab[lane*TS+d];
            }
            S.eqb[i*TE + lane] = s0;
            S.ekb_se[i*TE + lane] = s1;
            float s2 = 0.f, s3 = 0.f;
            #pragma unroll
            for (int d = 0; d < 24; d++) {
                s2 += qr[d] * S.dktab[lane*TS+d];
                s3 += kr[d] * S.dqtab[lane*TS+d];
            }
            S.dqb[i*TD + lane] = s2;
            S.dkb_sd[i*TD + lane] = s3;
            if (lane < 8) {
                int t = lane + 32;
                float s4 = 0.f, s5 = 0.f;
                #pragma unroll
                for (int d = 0; d < 24; d++) {
                    s4 += qr[d] * S.dktab[t*TS+d];
                    s5 += kr[d] * S.dqtab[t*TS+d];
                }
                S.dqb[i*TD + t] = s4;
                S.dkb_sd[i*TD + t] = s5;
            }
        }
    }
    __syncthreads();
    // phase 2: assemble scores (q row in registers, k column LDS conflict-free)
    const float scale = 0.2041241452319315f;  // 24^-0.5
    {
        #pragma unroll 1
        for (int r = 0; r < 8; r++) {
            int i = w * 8 + r;
            float qr[24];
            #pragma unroll
            for (int d = 0; d < 24; d++) qr[d] = S.q[i*24+d];
            #pragma unroll
            for (int half = 0; half < 2; half++) {
                int j = lane + half * 32;
                float s = 0.f;
                #pragma unroll
                for (int d = 0; d < 24; d++) s += qr[d] * S.k25[j*TS+d];
                int e = i*64 + j;
                int c = S.ct[e], dd = S.dt[e];
                s += S.eqb[i*TE+c] + S.ekb_se[j*TE+c] + S.dqb[i*TD+dd] + S.dkb_sd[j*TD+dd] + S.amat[e];
                s *= scale;
                if (S.maskv[j]) s = -1e30f;
                S.amat[e] = s;
            }
        }
    }
    __syncthreads();
    // phase 3: zero scatter bins + row softmax + toeplitz
    for (int e = tid; e < NN * TE; e += 256) S.ekb_se[e] = 0.f;
    for (int e = tid; e < NN * TD; e += 256) S.dkb_sd[e] = 0.f;
    {
        #pragma unroll
        for (int r = 0; r < 8; r++) {
            int i = w * 8 + r;
            float a0 = S.amat[i*64 + lane], a1 = S.amat[i*64 + 32 + lane];
            float m = fmaxf(a0, a1);
            #pragma unroll
            for (int o = 16; o; o >>= 1) m = fmaxf(m, __shfl_xor_sync(0xffffffffu, m, o));
            float e0 = __expf(a0 - m), e1 = __expf(a1 - m);
            float ssum = e0 + e1;
            #pragma unroll
            for (int o = 16; o; o >>= 1) ssum += __shfl_xor_sync(0xffffffffu, ssum, o);
            float inv = 1.f / ssum;
            int j0 = lane, j1 = lane + 32;
            float t0 = (j0 >= i) ? S.trow[j0 - i] : S.tcol[i - j0];
            float t1 = (j1 >= i) ? S.trow[j1 - i] : S.tcol[i - j1];
            S.amat[i*64 + j0] = e0 * inv * t0;
            S.amat[i*64 + j1] = e1 * inv * t1;
        }
    }
    __syncthreads();
    // phase 4: type scatter into s_e / s_d
    for (int e = tid; e < NN * NN; e += 256) {
        int i = e >> 6;
        float a = S.amat[e];
        atomicAdd(&S.ekb_se[i*TE + S.ct[e]], a);
        atomicAdd(&S.dkb_sd[i*TD + S.dt[e]], a);
    }
    __syncthreads();
    // phase 5: z = a@v + s_e@Ev + s_d@Dv, write tf32 transposed [b*n][h*24+d]
    for (int e = tid; e < NN * DK; e += 256) {
        int i = e / 24, d = e - i * 24;
        float z = 0.f;
        const float* arow = S.amat + i * 64;
        #pragma unroll 8
        for (int j = 0; j < 64; j++) z += arow[j] * S.v[j*24 + d];
        const float* se = S.ekb_se + i * TE;
        #pragma unroll 8
        for (int t = 0; t < 32; t++) z += se[t] * S.evtab[t*TS + d];
        const float* sd = S.dkb_sd + i * TD;
        #pragma unroll 8
        for (int t = 0; t < 40; t++) z += sd[t] * S.dvtab[t*TS + d];
        g_z32[(b * NN + i) * 768 + h * 24 + d] = f2tf32(z);
    }
}

// ---------------- launch --------------------------------------------------------
extern "C" void kernel_launch(void* const* d_in, const int* in_sizes, int n_in,
                              void* d_out, int out_size) {
    const float* node   = (const float*)d_in[0];
    const int*   distv  = (const int*)d_in[1];
    const int*   conn   = (const int*)d_in[2];
    const int*   traj   = (const int*)d_in[3];
    const unsigned char* mask = (const unsigned char*)d_in[4];
    const float* W_qkv  = (const float*)d_in[5];
    const float* b_qkv  = (const float*)d_in[6];
    const float* W_out  = (const float*)d_in[7];
    const float* b_out  = (const float*)d_in[8];
    const float* Eq     = (const float*)d_in[9];
    const float* Ek     = (const float*)d_in[10];
    const float* Dq     = (const float*)d_in[11];
    const float* Dk     = (const float*)d_in[12];
    const float* pemb   = (const float*)d_in[13];
    const float* ppw    = (const float*)d_in[14];
    const float* Ev     = (const float*)d_in[15];
    const float* Dv     = (const float*)d_in[16];
    const float* Tr     = (const float*)d_in[17];
    const float* Tc     = (const float*)d_in[18];
    float* out = (float*)d_out;

    int attn_smem = (int)sizeof(AttnSmem);
    int path_smem = (VP * HH + 64 * 33) * (int)sizeof(float);
    int gemm_smem = 4 * 128 * 36 * 4;
    cudaFuncSetAttribute(attn_kernel, cudaFuncAttributeMaxDynamicSharedMemorySize, attn_smem);
    cudaFuncSetAttribute(path_kernel, cudaFuncAttributeMaxDynamicSharedMemorySize, path_smem);
    cudaFuncSetAttribute(mma_gemm_kernel<true>,  cudaFuncAttributeMaxDynamicSharedMemorySize, gemm_smem);
    cudaFuncSetAttribute(mma_gemm_kernel<false>, cudaFuncAttributeMaxDynamicSharedMemorySize, gemm_smem);

    uint32_t *wq32p, *wo32p, *a32p, *z32p;
    cudaGetSymbolAddress((void**)&wq32p, g_wq32);
    cudaGetSymbolAddress((void**)&wo32p, g_wo32);
    cudaGetSymbolAddress((void**)&a32p, g_a32);
    cudaGetSymbolAddress((void**)&z32p, g_z32);

    conv_a_kernel<<<6144, 256>>>(node);
    convT_kernel<2304><<<dim3(72, 24), dim3(32, 8)>>>(W_qkv, wq32p);
    convT_kernel<768><<<dim3(24, 24), dim3(32, 8)>>>(W_out, wo32p);

    mma_gemm_kernel<true><<<dim3(2304/128, 8192/128), 256, gemm_smem>>>(a32p, wq32p, b_qkv, nullptr);
    path_kernel<<<BB * 2, 256, path_smem>>>(traj, distv, pemb, ppw);
    attn_kernel<<<dim3(HH, BB), 256, attn_smem>>>(conn, distv, mask,
                                                  Eq, Ek, Dq, Dk, Ev, Dv, Tr, Tc);
    mma_gemm_kernel<false><<<dim3(768/128, 8192/128), 256, gemm_smem>>>(z32p, wo32p, b_out, out);
}

// round 4
// speedup vs baseline: 1.3199x; 1.3199x over previous
#include <cuda_runtime.h>
#include <cuda_bf16.h>
#include <math.h>
#include <cstdint>

// Problem constants
#define BB 128
#define NN 64
#define DD 768
#define HH 32
#define DK 24
#define LL 4
#define TE 32
#define TD 40
#define VP 512

// ---------------- scratch (device globals; no allocations allowed) -------------
__device__ float g_q[BB*HH*NN*DK];   // [b,h,n,d]
__device__ float g_k[BB*HH*NN*DK];
__device__ float g_v[BB*HH*NN*DK];
__device__ float g_pb[BB*HH*NN*NN];  // path bias [b,h,i,j]
__device__ uint32_t g_a32[8192*768];    // node_reps as tf32
__device__ uint32_t g_wq32[2304*768];   // W_qkv transposed [n][k], tf32
__device__ uint32_t g_wo32[768*768];    // W_out transposed [n][k], tf32
__device__ uint32_t g_z32[8192*768];    // z as tf32, [b*n][h*dk]

// ---------------- tf32 helpers ---------------------------------------------------
__device__ __forceinline__ uint32_t f2tf32(float f) {
    uint32_t r;
    asm("cvt.rna.tf32.f32 %0, %1;" : "=r"(r) : "f"(f));
    return r;
}

__device__ __forceinline__ void mma_tf32(float* d, const uint32_t* a, const uint32_t* b) {
    asm volatile("mma.sync.aligned.m16n8k8.row.col.f32.tf32.tf32.f32 "
        "{%0,%1,%2,%3}, {%4,%5,%6,%7}, {%8,%9}, {%0,%1,%2,%3};"
        : "+f"(d[0]), "+f"(d[1]), "+f"(d[2]), "+f"(d[3])
        : "r"(a[0]), "r"(a[1]), "r"(a[2]), "r"(a[3]), "r"(b[0]), "r"(b[1]));
}

__device__ __forceinline__ void cp16(uint32_t saddr, const void* g) {
    asm volatile("cp.async.ca.shared.global [%0], [%1], 16;" :: "r"(saddr), "l"(g));
}

// ---------------- conversion pre-passes -----------------------------------------
__global__ void __launch_bounds__(256) conv_a_kernel(const float* __restrict__ X) {
    int idx = (blockIdx.x * 256 + threadIdx.x) * 4;
    float4 v = *(const float4*)(X + idx);
    uint4 o = { f2tf32(v.x), f2tf32(v.y), f2tf32(v.z), f2tf32(v.w) };
    *(uint4*)(g_a32 + idx) = o;
}

template<int NLD>
__global__ void convT_kernel(const float* __restrict__ W, uint32_t* __restrict__ Wt) {
    __shared__ float t[32][33];
    int k0 = blockIdx.y * 32, n0 = blockIdx.x * 32;
    int x = threadIdx.x, y = threadIdx.y;  // 32x8
    for (int yy = y; yy < 32; yy += 8)
        t[yy][x] = W[(k0 + yy) * NLD + n0 + x];
    __syncthreads();
    for (int yy = y; yy < 32; yy += 8)
        Wt[(n0 + yy) * 768 + k0 + x] = f2tf32(t[x][yy]);
}

// ---------------- pipelined tensor-core GEMM ------------------------------------
// C[8192, NOUT] = A[8192,768] @ Wt^T, A and Wt pre-converted tf32, both K-major.
// CTA 128x128, 8 warps (2x4), warp tile 64x32, 2-stage cp.async pipeline.
template<bool QKV>
__global__ void __launch_bounds__(256, 2) mma_gemm_kernel(const uint32_t* __restrict__ A,
                                                          const uint32_t* __restrict__ Bt,
                                                          const float* __restrict__ bias,
                                                          float* __restrict__ Cout) {
    extern __shared__ uint32_t sm[];
    uint32_t* Abuf = sm;                 // [2][128*36]
    uint32_t* Bbuf = sm + 2 * 128 * 36;  // [2][128*36]
    int tid = threadIdx.x;
    int wid = tid >> 5, lane = tid & 31;
    int group = lane >> 2, four = lane & 3;
    int wm = (wid >> 2) * 64, wn = (wid & 3) * 32;
    int m0 = blockIdx.y * 128, c0 = blockIdx.x * 128;

    uint32_t sbase;
    { uint64_t a = __cvta_generic_to_shared(sm); sbase = (uint32_t)a; }

    int ldrow = tid >> 1;                 // 0..127 (2 threads per row)
    int ldch4 = (tid & 1) * 16;           // u32 offset of first chunk (0 or 16)
    const uint32_t* Arow = A + (m0 + ldrow) * 768 + ldch4;
    const uint32_t* Brow = Bt + (c0 + ldrow) * 768 + ldch4;
    uint32_t sArow = sbase + (ldrow * 36 + ldch4) * 4;
    uint32_t sBrow = sbase + (2 * 128 * 36 + ldrow * 36 + ldch4) * 4;

    // prologue: stage 0
    #pragma unroll
    for (int c = 0; c < 4; c++) {
        cp16(sArow + c * 16, Arow + c * 4);
        cp16(sBrow + c * 16, Brow + c * 4);
    }
    asm volatile("cp.async.commit_group;");

    float acc[4][4][4] = {};
    #pragma unroll 1
    for (int s = 0; s < 24; s++) {
        int buf = s & 1;
        if (s + 1 < 24) {
            int nb = (s + 1) & 1;
            uint32_t soA = sArow + nb * (128 * 36 * 4);
            uint32_t soB = sBrow + nb * (128 * 36 * 4);
            const uint32_t* gA = Arow + (s + 1) * 32;
            const uint32_t* gB = Brow + (s + 1) * 32;
            #pragma unroll
            for (int c = 0; c < 4; c++) {
                cp16(soA + c * 16, gA + c * 4);
                cp16(soB + c * 16, gB + c * 4);
            }
            asm volatile("cp.async.commit_group;");
            asm volatile("cp.async.wait_group 1;");
        } else {
            asm volatile("cp.async.wait_group 0;");
        }
        __syncthreads();
        const uint32_t* As = Abuf + buf * (128 * 36);
        const uint32_t* Bs = Bbuf + buf * (128 * 36);
        #pragma unroll
        for (int ks = 0; ks < 4; ks++) {
            int kk = ks * 8;
            uint32_t af[4][4], bf[4][2];
            #pragma unroll
            for (int fm = 0; fm < 4; fm++) {
                int r = wm + fm * 16 + group;
                af[fm][0] = As[r * 36 + kk + four];
                af[fm][1] = As[(r + 8) * 36 + kk + four];
                af[fm][2] = As[r * 36 + kk + four + 4];
                af[fm][3] = As[(r + 8) * 36 + kk + four + 4];
            }
            #pragma unroll
            for (int fn = 0; fn < 4; fn++) {
                int n = wn + fn * 8 + group;
                bf[fn][0] = Bs[n * 36 + kk + four];
                bf[fn][1] = Bs[n * 36 + kk + four + 4];
            }
            #pragma unroll
            for (int fm = 0; fm < 4; fm++)
                #pragma unroll
                for (int fn = 0; fn < 4; fn++)
                    mma_tf32(acc[fm][fn], af[fm], bf[fn]);
        }
        __syncthreads();
    }
    // epilogue
    #pragma unroll
    for (int fm = 0; fm < 4; fm++) {
        #pragma unroll
        for (int fn = 0; fn < 4; fn++) {
            #pragma unroll
            for (int r = 0; r < 4; r++) {
                int m = m0 + wm + fm * 16 + group + ((r >> 1) ? 8 : 0);
                int c = c0 + wn + fn * 8 + four * 2 + (r & 1);
                float val = acc[fm][fn][r] + bias[c];
                if (QKV) {
                    int b = m >> 6, n = m & 63;
                    int sx = c / 768, rem = c - sx * 768;
                    int h = rem / 24, d = rem % 24;
                    float* dst = (sx == 0) ? g_q : (sx == 1) ? g_k : g_v;
                    dst[((b * HH + h) * NN + n) * DK + d] = val;
                } else {
                    Cout[m * 768 + c] = val;
                }
            }
        }
    }
}

// ---------------- Kernel B: path bias -------------------------------------------
__global__ void __launch_bounds__(256) path_kernel(const int* __restrict__ traj,
                                                   const int* __restrict__ distv,
                                                   const float* __restrict__ pemb,
                                                   const float* __restrict__ ppw) {
    extern __shared__ float ps[];
    float* pe = ps;                  // 512*32
    float* stage = ps + VP * HH;     // 64*33
    int b = blockIdx.x >> 1;
    int i0 = (blockIdx.x & 1) * 32;
    int tid = threadIdx.x;
    for (int e = tid; e < VP * HH; e += 256) pe[e] = pemb[e];
    int w = tid >> 5, lane = tid & 31;
    float w0 = ppw[lane], w1 = ppw[32 + lane], w2 = ppw[64 + lane], w3 = ppw[96 + lane];
    __syncthreads();
    for (int ii = 0; ii < 32; ii++) {
        int i = i0 + ii;
        #pragma unroll
        for (int jj = 0; jj < 8; jj++) {
            int j = w * 8 + jj;
            int base = (((b * NN + i) * NN) + j) * 12;
            int myidx = (lane < 12) ? traj[base + lane] : 0;
            float acc = 0.f;
            #pragma unroll
            for (int t = 0; t < 12; t++) {
                int id = __shfl_sync(0xffffffffu, myidx, t);
                float wl = (t < 3) ? w0 : (t < 6) ? w1 : (t < 9) ? w2 : w3;
                acc += pe[id * 32 + lane] * wl;
            }
            float dn = fmaxf((float)distv[(b * NN + i) * NN + j], 1.f);
            stage[j * 33 + lane] = acc / dn;
        }
        __syncthreads();
        for (int e = tid; e < HH * NN; e += 256) {
            int hh = e >> 6, j = e & 63;
            g_pb[(((b * HH + hh) * NN + i) << 6) + j] = stage[j * 33 + hh];
        }
        __syncthreads();
    }
}

// ---------------- Kernel C: attention per (b,h) ---------------------------------
#define TS 25   // padded stride for k / tables (odd -> conflict-free lane-strided LDS)
struct AttnSmem {
    float q[NN*DK], k25[NN*TS], v[NN*DK];
    float ektab[TE*TS], eqtab[TE*TS];
    float dktab[TD*TS], dqtab[TD*TS];
    float evtab[TE*TS], dvtab[TD*TS];
    float eqb[NN*TE];                   // q_i . ektab[t]   [i][t]
    float dqb[NN*TD];                   // q_i . dktab[t]   [i][t]
    float ekb_se[TE*NN];                // ph1-2: k_j . eqtab[t] laid out [t][j]; later s_e [i][t]
    float dkb_sd[TD*NN];                // ph1-2: k_j . dqtab[t] laid out [t][j]; later s_d [i][t]
    float amat[NN*NN];
    float trow[NN], tcol[NN];
    unsigned char ct[NN*NN], dt[NN*NN], maskv[NN];
};

__device__ __forceinline__ float dot24s(const float* __restrict__ a, const float* __restrict__ b) {
    float s = 0.f;
    #pragma unroll
    for (int d = 0; d < 24; d++) s += a[d] * b[d];
    return s;
}

__global__ void __launch_bounds__(256) attn_kernel(const int* __restrict__ conn,
                                                   const int* __restrict__ distv,
                                                   const unsigned char* __restrict__ mask,
                                                   const float* __restrict__ Eq, const float* __restrict__ Ek,
                                                   const float* __restrict__ Dq, const float* __restrict__ Dk,
                                                   const float* __restrict__ Ev, const float* __restrict__ Dv,
                                                   const float* __restrict__ Tr, const float* __restrict__ Tc) {
    extern __shared__ char sraw[];
    AttnSmem& S = *reinterpret_cast<AttnSmem*>(sraw);
    int h = blockIdx.x, b = blockIdx.y;
    int tid = threadIdx.x;
    int w = tid >> 5, lane = tid & 31;
    int qoff = (b * HH + h) * NN * DK;
    for (int e = tid; e < NN * DK; e += 256) {
        int n = e / 24, d = e - n * 24;
        S.q[e] = g_q[qoff + e];
        S.k25[n * TS + d] = g_k[qoff + e];
        S.v[e] = g_v[qoff + e];
    }
    for (int e = tid; e < TE * DK; e += 256) {
        int t = e / 24, d = e - t * 24;
        S.ektab[t*TS+d] = Ek[(t * HH + h) * DK + d];
        S.eqtab[t*TS+d] = Eq[(t * HH + h) * DK + d];
        S.evtab[t*TS+d] = Ev[(t * HH + h) * DK + d];
    }
    for (int e = tid; e < TD * DK; e += 256) {
        int t = e / 24, d = e - t * 24;
        S.dktab[t*TS+d] = Dk[(t * HH + h) * DK + d];
        S.dqtab[t*TS+d] = Dq[(t * HH + h) * DK + d];
        S.dvtab[t*TS+d] = Dv[(t * HH + h) * DK + d];
    }
    if (tid < NN) {
        S.trow[tid] = Tr[h * NN + tid];
        S.tcol[tid] = Tc[h * NN + tid];
        S.maskv[tid] = mask[b * NN + tid];
    }
    int cdoff = b * NN * NN;
    int pboff = (b * HH + h) * NN * NN;
    for (int e = tid; e < NN * NN; e += 256) {
        S.ct[e] = (unsigned char)conn[cdoff + e];
        S.dt[e] = (unsigned char)distv[cdoff + e];
        S.amat[e] = g_pb[pboff + e];
    }
    __syncthreads();
    // phase 1: bias tables. q-side -> [i][t], k-side -> [t][j] (lane=j conflict-free)
    for (int e = tid; e < NN * TE; e += 256) { int i = e >> 5, t = e & 31; S.eqb[e] = dot24s(S.q + i*24, S.ektab + t*TS); }
    for (int e = tid; e < NN * TD; e += 256) { int i = e / 40, t = e - i * 40; S.dqb[e] = dot24s(S.q + i*24, S.dktab + t*TS); }
    for (int e = tid; e < TE * NN; e += 256) { int t = e >> 6, j = e & 63; S.ekb_se[e] = dot24s(S.k25 + j*TS, S.eqtab + t*TS); }
    for (int e = tid; e < TD * NN; e += 256) { int t = e >> 6, j = e & 63; S.dkb_sd[e] = dot24s(S.k25 + j*TS, S.dqtab + t*TS); }
    __syncthreads();
    // phase 2: assemble scores
    const float scale = 0.2041241452319315f;  // 24^-0.5
    for (int e = tid; e < NN * NN; e += 256) {
        int i = e >> 6, j = e & 63;
        float s = dot24s(S.q + i*24, S.k25 + j*TS);
        int c = S.ct[e], dd = S.dt[e];
        s += S.eqb[i*TE + c] + S.ekb_se[c*64 + j] + S.dqb[i*TD + dd] + S.dkb_sd[dd*64 + j] + S.amat[e];
        s *= scale;
        if (S.maskv[j]) s = -1e30f;
        S.amat[e] = s;
    }
    __syncthreads();
    // phase 3: zero scatter bins + row softmax + toeplitz
    for (int e = tid; e < NN * TE; e += 256) S.ekb_se[e] = 0.f;
    for (int e = tid; e < NN * TD; e += 256) S.dkb_sd[e] = 0.f;
    {
        #pragma unroll
        for (int r = 0; r < 8; r++) {
            int i = w * 8 + r;
            float a0 = S.amat[i*64 + lane], a1 = S.amat[i*64 + 32 + lane];
            float m = fmaxf(a0, a1);
            #pragma unroll
            for (int o = 16; o; o >>= 1) m = fmaxf(m, __shfl_xor_sync(0xffffffffu, m, o));
            float e0 = __expf(a0 - m), e1 = __expf(a1 - m);
            float ssum = e0 + e1;
            #pragma unroll
            for (int o = 16; o; o >>= 1) ssum += __shfl_xor_sync(0xffffffffu, ssum, o);
            float inv = 1.f / ssum;
            int j0 = lane, j1 = lane + 32;
            float t0 = (j0 >= i) ? S.trow[j0 - i] : S.tcol[i - j0];
            float t1 = (j1 >= i) ? S.trow[j1 - i] : S.tcol[i - j1];
            S.amat[i*64 + j0] = e0 * inv * t0;
            S.amat[i*64 + j1] = e1 * inv * t1;
        }
    }
    __syncthreads();
    // phase 4: type scatter into s_e / s_d ([i][t] bins)
    for (int e = tid; e < NN * NN; e += 256) {
        int i = e >> 6;
        float a = S.amat[e];
        atomicAdd(&S.ekb_se[i*TE + S.ct[e]], a);
        atomicAdd(&S.dkb_sd[i*TD + S.dt[e]], a);
    }
    __syncthreads();
    // phase 5: z = a@v + s_e@Ev + s_d@Dv, write tf32 transposed [b*n][h*24+d]
    for (int e = tid; e < NN * DK; e += 256) {
        int i = e / 24, d = e - i * 24;
        float z = 0.f;
        const float* arow = S.amat + i * 64;
        #pragma unroll 8
        for (int j = 0; j < 64; j++) z += arow[j] * S.v[j*24 + d];
        const float* se = S.ekb_se + i * TE;
        #pragma unroll 8
        for (int t = 0; t < 32; t++) z += se[t] * S.evtab[t*TS + d];
        const float* sd = S.dkb_sd + i * TD;
        #pragma unroll 8
        for (int t = 0; t < 40; t++) z += sd[t] * S.dvtab[t*TS + d];
        g_z32[(b * NN + i) * 768 + h * 24 + d] = f2tf32(z);
    }
}

// ---------------- launch --------------------------------------------------------
extern "C" void kernel_launch(void* const* d_in, const int* in_sizes, int n_in,
                              void* d_out, int out_size) {
    const float* node   = (const float*)d_in[0];
    const int*   distv  = (const int*)d_in[1];
    const int*   conn   = (const int*)d_in[2];
    const int*   traj   = (const int*)d_in[3];
    const unsigned char* mask = (const unsigned char*)d_in[4];
    const float* W_qkv  = (const float*)d_in[5];
    const float* b_qkv  = (const float*)d_in[6];
    const float* W_out  = (const float*)d_in[7];
    const float* b_out  = (const float*)d_in[8];
    const float* Eq     = (const float*)d_in[9];
    const float* Ek     = (const float*)d_in[10];
    const float* Dq     = (const float*)d_in[11];
    const float* Dk     = (const float*)d_in[12];
    const float* pemb   = (const float*)d_in[13];
    const float* ppw    = (const float*)d_in[14];
    const float* Ev     = (const float*)d_in[15];
    const float* Dv     = (const float*)d_in[16];
    const float* Tr     = (const float*)d_in[17];
    const float* Tc     = (const float*)d_in[18];
    float* out = (float*)d_out;

    int attn_smem = (int)sizeof(AttnSmem);
    int path_smem = (VP * HH + 64 * 33) * (int)sizeof(float);
    int gemm_smem = 4 * 128 * 36 * 4;
    cudaFuncSetAttribute(attn_kernel, cudaFuncAttributeMaxDynamicSharedMemorySize, attn_smem);
    cudaFuncSetAttribute(path_kernel, cudaFuncAttributeMaxDynamicSharedMemorySize, path_smem);
    cudaFuncSetAttribute(mma_gemm_kernel<true>,  cudaFuncAttributeMaxDynamicSharedMemorySize, gemm_smem);
    cudaFuncSetAttribute(mma_gemm_kernel<false>, cudaFuncAttributeMaxDynamicSharedMemorySize, gemm_smem);

    uint32_t *wq32p, *wo32p, *a32p, *z32p;
    cudaGetSymbolAddress((void**)&wq32p, g_wq32);
    cudaGetSymbolAddress((void**)&wo32p, g_wo32);
    cudaGetSymbolAddress((void**)&a32p, g_a32);
    cudaGetSymbolAddress((void**)&z32p, g_z32);

    conv_a_kernel<<<6144, 256>>>(node);
    convT_kernel<2304><<<dim3(72, 24), dim3(32, 8)>>>(W_qkv, wq32p);
    convT_kernel<768><<<dim3(24, 24), dim3(32, 8)>>>(W_out, wo32p);

    mma_gemm_kernel<true><<<dim3(2304/128, 8192/128), 256, gemm_smem>>>(a32p, wq32p, b_qkv, nullptr);
    path_kernel<<<BB * 2, 256, path_smem>>>(traj, distv, pemb, ppw);
    attn_kernel<<<dim3(HH, BB), 256, attn_smem>>>(conn, distv, mask,
                                                  Eq, Ek, Dq, Dk, Ev, Dv, Tr, Tc);
    mma_gemm_kernel<false><<<dim3(768/128, 8192/128), 256, gemm_smem>>>(z32p, wo32p, b_out, out);
}